// round 7
// baseline (speedup 1.0000x reference)
#include <cuda_runtime.h>
#include <cstdint>
#include <cstddef>
#include <math.h>

#define FULLMASK 0xFFFFFFFFu

// ----------------------------- static scratch ------------------------------
__device__ __align__(16) unsigned       g_xp[8192 * 28];    // packed input rows
__device__ __align__(16) unsigned       g_a1[8192 * 400];   // L1 acts, bit c = channel (13.1 MB)
__device__ __align__(16) unsigned short g_a2[8192 * 144];   // L2 acts, bit c = channel (2.36 MB)

__device__ unsigned       g_w1p[32 * 9];     // [f][u], bits v
__device__ unsigned       g_w2p[16 * 81];    // [f][tap], bits c(32)
__device__ unsigned short g_w3p[8 * 81];     // [f][tap], bits c(16)
__device__ unsigned       g_wlp[10 * 4];     // [f][p], bit (c + 8q), pos=4p+q
__device__ float          g_sbl[10];

__device__ int g_T[784];         // batch counts of sign(x) bits per input pixel
__device__ int g_S1[400 * 32];   // batch counts of a1 bits per (pixel, ch)
__device__ int g_S2[144 * 16];   // batch counts of a2 bits per (pixel, ch)
__device__ int g_lim1[32], g_lim2[16], g_lim3[8];  // popcount limits (<=)
__device__ int g_c1, g_c2;       // last-block counters

// ------------------------------ zero ---------------------------------------
__global__ void zerok() {
    int t = blockIdx.x * 256 + threadIdx.x;
    if (t < 12800) g_S1[t] = 0;
    if (t < 2304)  g_S2[t] = 0;
    if (t < 784)   g_T[t]  = 0;
    if (t == 0) { g_c1 = 0; g_c2 = 0; }
}

// ------------------- binarize x + batch counts + weight prep ---------------
__global__ __launch_bounds__(256) void binxprep(
    const float* __restrict__ x,  const float* __restrict__ w1,
    const float* __restrict__ w2, const float* __restrict__ w3,
    const float* __restrict__ wl, const float* __restrict__ bl) {
    __shared__ int Ts[784];
    int tid = threadIdx.x;
    for (int t = tid; t < 784; t += 256) Ts[t] = 0;
    if (blockIdx.x == 0) {                 // weight packing piggybacks on block 0
        for (int idx = tid; idx < 2282; idx += 256) {
            if (idx < 288) {
                int f = idx / 9, u = idx % 9; unsigned m = 0;
                for (int v = 0; v < 9; v++)
                    if (w1[f * 81 + u * 9 + v] >= 0.f) m |= 1u << v;
                g_w1p[idx] = m;
            } else if (idx < 1584) {
                int e = idx - 288, f = e / 81, t2 = e % 81; unsigned m = 0;
                for (int c = 0; c < 32; c++)
                    if (w2[f * 2592 + c * 81 + t2] >= 0.f) m |= 1u << c;
                g_w2p[e] = m;
            } else if (idx < 2232) {
                int e = idx - 1584, f = e / 81, t3 = e % 81; unsigned m = 0;
                for (int c = 0; c < 16; c++)
                    if (w3[f * 1296 + c * 81 + t3] >= 0.f) m |= 1u << c;
                g_w3p[e] = (unsigned short)m;
            } else if (idx < 2272) {
                int e = idx - 2232, f = e / 4, p = e % 4; unsigned m = 0;
                for (int q = 0; q < 4; q++)
                    for (int c = 0; c < 8; c++)
                        if (wl[f * 128 + c * 16 + (4 * p + q)] >= 0.f) m |= 1u << (c + 8 * q);
                g_wlp[e] = m;
            } else {
                int f = idx - 2272;
                g_sbl[f] = (bl[f] >= 0.f) ? 1.f : -1.f;
            }
        }
    }
    __syncthreads();
    int lane = tid & 31, w = tid >> 5;
    int n = blockIdx.x * 8 + w;
    const float* xi = x + (size_t)n * 784;
    unsigned myrow = 0;
    for (int row = 0; row < 28; row++) {
        float v = (lane < 28) ? xi[row * 28 + lane] : -1.f;
        unsigned m = __ballot_sync(FULLMASK, v >= 0.f);
        if (lane == row) myrow = m;
        if (lane < 28 && ((m >> lane) & 1u)) atomicAdd(&Ts[row * 28 + lane], 1);
    }
    if (lane < 28) g_xp[n * 28 + lane] = myrow;
    __syncthreads();
    for (int t = tid; t < 784; t += 256) atomicAdd(&g_T[t], Ts[t]);
}

// ------------------------------ thresh1 ------------------------------------
__global__ void thresh1() {
    __shared__ int Tc[784];
    __shared__ int R[28 * 9];
    __shared__ int A[81];
    int tid = threadIdx.x;
    for (int t = tid; t < 784; t += 256) Tc[t] = g_T[t];
    __syncthreads();
    for (int e = tid; e < 252; e += 256) {     // row-window sums
        int r = e / 9, v = e % 9, s = 0;
        for (int j = 0; j < 20; j++) s += Tc[r * 28 + j + v];
        R[e] = s;
    }
    __syncthreads();
    for (int e = tid; e < 81; e += 256) {
        int u = e / 9, v = e % 9, s = 0;
        for (int i = 0; i < 20; i++) s += R[(i + u) * 9 + v];
        A[e] = s;
    }
    __syncthreads();
    if (tid < 32) {
        long long s = 0;
        for (int u = 0; u < 9; u++) {
            unsigned wrow = g_w1p[tid * 9 + u];
            for (int v = 0; v < 9; v++) {
                long long a = 2LL * A[u * 9 + v] - 3276800LL;
                s += ((wrow >> v) & 1u) ? a : -a;
            }
        }
        int t1 = (int)ceil((double)s / 3276800.0);
        g_lim1[tid] = (81 - t1) >> 1;     // y>=t1 <=> popc-acc <= lim
    }
}

// ------------------------------ conv1 (emits packed a1) --------------------
__global__ __launch_bounds__(256) void conv1k() {
    __shared__ unsigned ws[288];
    __shared__ unsigned xr[8][28];
    __shared__ int lim[32];
    int tid = threadIdx.x, lane = tid & 31, w = tid >> 5;
    for (int t = tid; t < 288; t += 256) ws[t] = g_w1p[t];
    if (tid < 32) lim[tid] = g_lim1[tid];
    int n = blockIdx.x * 8 + w;
    if (lane < 28) xr[w][lane] = g_xp[n * 28 + lane];
    __syncthreads();
    unsigned w9[9];
#pragma unroll
    for (int u = 0; u < 9; u++) w9[u] = ws[lane * 9 + u];
    int mylim = lim[lane];
    const unsigned* xrw = xr[w];
    unsigned* outp = &g_a1[n * 400];
    for (int i = 0; i < 20; i++) {
        unsigned r[9];
#pragma unroll
        for (int u = 0; u < 9; u++) r[u] = xrw[i + u];
        unsigned myw = 0;
#pragma unroll
        for (int j = 0; j < 20; j++) {
            int acc = 0;
#pragma unroll
            for (int u = 0; u < 9; u++)
                acc += __popc(((r[u] >> j) & 0x1FFu) ^ w9[u]);
            unsigned b = __ballot_sync(FULLMASK, acc <= mylim);
            if (lane == j) myw = b;
        }
        if (lane < 20) outp[i * 20 + lane] = myw;
    }
}

// ---------------- suma1: count a1 bits; last block computes thresh2 --------
__global__ __launch_bounds__(256) void suma1k() {
    int tg = blockIdx.x * 256 + threadIdx.x;       // 25600 = 400 px * 64 chunks
    int p = tg % 400, chunk = tg / 400;
    int cnt[32];
#pragma unroll
    for (int c = 0; c < 32; c++) cnt[c] = 0;
    const unsigned* base = &g_a1[(size_t)chunk * 128 * 400 + p];
    for (int k = 0; k < 128; k++) {
        unsigned wd = base[k * 400];
#pragma unroll
        for (int c = 0; c < 32; c++) cnt[c] += (wd >> c) & 1u;
    }
#pragma unroll
    for (int c = 0; c < 32; c++) atomicAdd(&g_S1[p * 32 + c], cnt[c]);

    __shared__ int R[20 * 9 * 32];
    __shared__ int WS[2592];
    __shared__ int lastf;
    __threadfence();
    if (threadIdx.x == 0) lastf = (atomicAdd(&g_c1, 1) == (int)gridDim.x - 1);
    __syncthreads();
    if (!lastf) return;
    __threadfence();
    int tid = threadIdx.x;
    for (int e = tid; e < 5760; e += 256) {        // R[(r*9+v)*32+c]
        int c = e & 31, rv = e >> 5, r = rv / 9, v = rv % 9, s = 0;
        for (int j = 0; j < 12; j++) s += g_S1[(r * 20 + j + v) * 32 + c];
        R[e] = s;
    }
    __syncthreads();
    for (int e = tid; e < 2592; e += 256) {        // WS[tap*32+c] in +/- form
        int c = e & 31, uv = e >> 5, u = uv / 9, v = uv % 9, s = 0;
        for (int i = 0; i < 12; i++) s += R[((i + u) * 9 + v) * 32 + c];
        WS[e] = 2 * s - 1179648;
    }
    __syncthreads();
    int lane = tid & 31, wp = tid >> 5;
    for (int ff = 0; ff < 2; ff++) {
        int f = wp * 2 + ff;
        long long s = 0;
        for (int t = lane; t < 81; t += 32) {
            unsigned wdw = g_w2p[f * 81 + t];
#pragma unroll
            for (int c = 0; c < 32; c++) {
                int term = WS[t * 32 + c];
                s += ((wdw >> c) & 1u) ? term : -term;
            }
        }
        for (int o = 16; o > 0; o >>= 1) s += __shfl_down_sync(FULLMASK, s, o);
        if (lane == 0) {
            int t2 = (int)ceil((double)s / 1179648.0);
            g_lim2[f] = (2592 - t2) >> 1;
        }
    }
}

// ------------------------------ conv2 (emits packed a2) --------------------
__global__ __launch_bounds__(256) void conv2k() {
    __shared__ unsigned xs[1600];       // 4 images x 400
    __shared__ unsigned ws[1296];
    __shared__ int lim[16];
    int tid = threadIdx.x, lane = tid & 31;
    int n0 = blockIdx.x * 4;
    for (int t = tid; t < 1600; t += 256) xs[t] = g_a1[(size_t)n0 * 400 + t];
    for (int t = tid; t < 1296; t += 256) ws[t] = g_w2p[t];
    if (tid < 16) lim[tid] = g_lim2[tid];
    __syncthreads();
    for (int it = 0; it < 3; it++) {
        int t = tid + it * 256;
        int f = t & 15, r = t >> 4;               // r in 0..47
        int img = r / 12, i = r % 12;
        const unsigned* xb = &xs[img * 400 + i * 20];
        const unsigned* wb = &ws[f * 81];
        int acc[12];
#pragma unroll
        for (int jj = 0; jj < 12; jj++) acc[jj] = 0;
        for (int u = 0; u < 9; u++) {             // NOT unrolled: keep I$ small
            unsigned xw[20];
#pragma unroll
            for (int k = 0; k < 20; k++) xw[k] = xb[u * 20 + k];
#pragma unroll
            for (int v = 0; v < 9; v++) {
                unsigned wv = wb[u * 9 + v];
#pragma unroll
                for (int jj = 0; jj < 12; jj++)
                    acc[jj] += __popc(xw[jj + v] ^ wv);
            }
        }
        int limf = lim[f];
        unsigned myword = 0;
#pragma unroll
        for (int jj = 0; jj < 12; jj++) {
            unsigned b = __ballot_sync(FULLMASK, acc[jj] <= limf);
            if ((lane & 15) == jj) myword = (lane < 16) ? (b & 0xFFFFu) : (b >> 16);
        }
        if ((lane & 15) < 12)
            g_a2[(size_t)(n0 + img) * 144 + i * 12 + (lane & 15)] = (unsigned short)myword;
    }
}

// ---------------- suma2: count a2 bits; last block computes thresh3 --------
__global__ __launch_bounds__(256) void suma2k() {
    int tg = blockIdx.x * 256 + threadIdx.x;       // 9216 = 144 px * 64 chunks
    int p = tg % 144, chunk = tg / 144;
    int cnt[16];
#pragma unroll
    for (int c = 0; c < 16; c++) cnt[c] = 0;
    const unsigned short* base = &g_a2[(size_t)chunk * 128 * 144 + p];
    for (int k = 0; k < 128; k++) {
        unsigned wd = base[k * 144];
#pragma unroll
        for (int c = 0; c < 16; c++) cnt[c] += (wd >> c) & 1u;
    }
#pragma unroll
    for (int c = 0; c < 16; c++) atomicAdd(&g_S2[p * 16 + c], cnt[c]);

    __shared__ int WS[1296];
    __shared__ int lastf;
    __threadfence();
    if (threadIdx.x == 0) lastf = (atomicAdd(&g_c2, 1) == (int)gridDim.x - 1);
    __syncthreads();
    if (!lastf) return;
    __threadfence();
    int tid = threadIdx.x;
    for (int e = tid; e < 1296; e += 256) {        // WS[tap*16+c] in +/- form
        int c = e & 15, uv = e >> 4, u = uv / 9, v = uv % 9, s = 0;
        for (int i = 0; i < 4; i++)
            for (int j = 0; j < 4; j++)
                s += g_S2[((i + u) * 12 + (j + v)) * 16 + c];
        WS[e] = 2 * s - 131072;
    }
    __syncthreads();
    int lane = tid & 31, f = tid >> 5;             // 8 warps = 8 filters
    long long s = 0;
    for (int t = lane; t < 81; t += 32) {
        unsigned wdw = g_w3p[f * 81 + t];
#pragma unroll
        for (int c = 0; c < 16; c++) {
            int term = WS[(t << 4) + c];
            s += ((wdw >> c) & 1u) ? term : -term;
        }
    }
    for (int o = 16; o > 0; o >>= 1) s += __shfl_down_sync(FULLMASK, s, o);
    if (lane == 0) {
        int t3 = (int)ceil((double)s / 131072.0);
        g_lim3[f] = (1296 - t3) >> 1;
    }
}

// --------------- conv3 + binarize + linear layer, fused --------------------
__global__ __launch_bounds__(256) void conv34k(float* __restrict__ out) {
    __shared__ unsigned short xs[2][144];
    __shared__ unsigned short ws[8 * 88];   // stride 88 kills bank conflicts
    __shared__ int lim[8];
    __shared__ unsigned a3s[2][4];
    int tid = threadIdx.x;
    int n0 = blockIdx.x * 2;
    for (int t = tid; t < 288; t += 256) {
        int img = t / 144, pp = t % 144;
        xs[img][pp] = g_a2[(size_t)(n0 + img) * 144 + pp];
    }
    for (int t = tid; t < 648; t += 256) {
        int f = t / 81, k = t % 81;
        ws[f * 88 + k] = g_w3p[t];
    }
    if (tid < 8) lim[tid] = g_lim3[tid];
    __syncthreads();
    int half = tid >> 7, ht = tid & 127;
    int f = ht & 7, pix = ht >> 3, i = pix >> 2, j = pix & 3;
    const unsigned short* xb = &xs[half][i * 12 + j];
    const unsigned short* wb = &ws[f * 88];
    int acc = 0;
#pragma unroll
    for (int u = 0; u < 9; u++)
#pragma unroll
        for (int v = 0; v < 9; v++)
            acc += __popc((unsigned)(xb[u * 12 + v] ^ wb[u * 9 + v]));
    // ballot word w = pix>>2 with bit lane = (pix&3)*8+f — exactly g_wlp layout
    unsigned bw = __ballot_sync(FULLMASK, acc <= lim[f]);
    if ((tid & 31) == 0) a3s[half][ht >> 5] = bw;
    __syncthreads();
    if (ht < 10) {
        const unsigned* wp = &g_wlp[ht * 4];
        int pop = 0;
#pragma unroll
        for (int p4 = 0; p4 < 4; p4++) pop += __popc(a3s[half][p4] ^ wp[p4]);
        out[(n0 + half) * 10 + ht] = (float)(128 - 2 * pop) + g_sbl[ht];
    }
}

// ------------------------------ launch -------------------------------------
// Inputs identified BY ELEMENT COUNT (all 9 distinct): robust to any order.
extern "C" void kernel_launch(void* const* d_in, const int* in_sizes, int n_in,
                              void* d_out, int out_size) {
    (void)out_size;
    const float *x = 0, *w1 = 0, *w2 = 0, *w3 = 0, *wl = 0, *bl = 0;
    for (int i = 0; i < n_in; i++) {
        const float* p = (const float*)d_in[i];
        switch (in_sizes[i]) {
            case 6422528: x  = p; break;
            case 2592:    w1 = p; break;
            case 41472:   w2 = p; break;
            case 10368:   w3 = p; break;
            case 1280:    wl = p; break;
            case 10:      bl = p; break;
            default: break;   // b1/b2/b3 cancel under BN+sign
        }
    }
    zerok   <<<50,   256>>>();
    binxprep<<<1024, 256>>>(x, w1, w2, w3, wl, bl);
    thresh1 <<<1,    256>>>();
    conv1k  <<<1024, 256>>>();
    suma1k  <<<100,  256>>>();
    conv2k  <<<2048, 256>>>();
    suma2k  <<<36,   256>>>();
    conv34k <<<4096, 256>>>((float*)d_out);
}